// round 2
// baseline (speedup 1.0000x reference)
#include <cuda_runtime.h>
#include <cuda_bf16.h>

#define TFR 4096
#define DM 128
#define LQ 64
#define NG 16
#define FD 2048
#define GFD 512
#define NTOK (TFR * NG)
#define LNE 1e-5f

// ---------------- device-global scratch (allocation-free rule) --------------
__device__ float g_lnvis[TFR * DM];
__device__ float g_text[NG * DM];
__device__ float g_Kf[NG * DM];
__device__ float g_Vf[NG * DM];
__device__ float g_K[2][TFR * DM];
__device__ float g_V[2][TFR * DM];
__device__ float g_t[NTOK * DM];
__device__ float g_tq[NTOK * DM];
__device__ float g_Qp[NTOK * DM];

__device__ __forceinline__ float warp_sum(float v) {
#pragma unroll
    for (int o = 16; o > 0; o >>= 1) v += __shfl_xor_sync(0xffffffffu, v, o);
    return v;
}

// text = g @ W_txt ; Kf = text @ Wk_f ; Vf = text @ Wv_f  (1 block, 128 thr)
__global__ void text_kernel(const float* __restrict__ g,
                            const float* __restrict__ Wtxt,
                            const float* __restrict__ Wkf,
                            const float* __restrict__ Wvf) {
    __shared__ float sg[NG * GFD];
    int tid = threadIdx.x;
    for (int i = tid; i < NG * GFD; i += 128) sg[i] = g[i];
    __syncthreads();
    int c = tid;
    float acc[NG];
#pragma unroll
    for (int r = 0; r < NG; r++) acc[r] = 0.f;
    for (int k = 0; k < GFD; k++) {
        float w = Wtxt[k * DM + c];
#pragma unroll
        for (int r = 0; r < NG; r++) acc[r] += sg[r * GFD + k] * w;
    }
#pragma unroll
    for (int r = 0; r < NG; r++) g_text[r * DM + c] = acc[r];
    __syncthreads();
    float* st = sg;  // reuse
#pragma unroll
    for (int r = 0; r < NG; r++) st[r * DM + c] = acc[r];
    __syncthreads();
    float a1[NG], a2[NG];
#pragma unroll
    for (int r = 0; r < NG; r++) { a1[r] = 0.f; a2[r] = 0.f; }
    for (int k = 0; k < DM; k++) {
        float w1 = Wkf[k * DM + c];
        float w2 = Wvf[k * DM + c];
#pragma unroll
        for (int r = 0; r < NG; r++) {
            float tv = st[r * DM + k];
            a1[r] += tv * w1;
            a2[r] += tv * w2;
        }
    }
#pragma unroll
    for (int r = 0; r < NG; r++) {
        g_Kf[r * DM + c] = a1[r];
        g_Vf[r * DM + c] = a2[r];
    }
}

// lnvis = LN(long_feature @ W_vis)   (64 blocks x 64 rows, 256 thr)
__global__ void visual_ln_kernel(const float* __restrict__ LF,
                                 const float* __restrict__ Wv) {
    __shared__ float sA[64][33];
    __shared__ float sB[32][132];
    __shared__ float ps[64][16], pq[64][16];
    __shared__ float smu[64], srs[64];
    int tid = threadIdx.x;
    int row0 = blockIdx.x * 64;
    int tr = tid >> 4, tc = tid & 15;
    float acc[4][8];
#pragma unroll
    for (int i = 0; i < 4; i++)
#pragma unroll
        for (int j = 0; j < 8; j++) acc[i][j] = 0.f;
    for (int kc = 0; kc < FD; kc += 32) {
#pragma unroll
        for (int i = 0; i < 8; i++) {
            int e = i * 256 + tid, r = e >> 5, k = e & 31;
            sA[r][k] = LF[(size_t)(row0 + r) * FD + kc + k];
        }
#pragma unroll
        for (int i = 0; i < 16; i++) {
            int e = i * 256 + tid, k = e >> 7, cc = e & 127;
            sB[k][cc] = Wv[(kc + k) * DM + cc];
        }
        __syncthreads();
#pragma unroll
        for (int k = 0; k < 32; k++) {
            float4 b0 = *(const float4*)&sB[k][tc * 8];
            float4 b1 = *(const float4*)&sB[k][tc * 8 + 4];
            float bb[8] = {b0.x, b0.y, b0.z, b0.w, b1.x, b1.y, b1.z, b1.w};
#pragma unroll
            for (int i = 0; i < 4; i++) {
                float a = sA[tr * 4 + i][k];
#pragma unroll
                for (int j = 0; j < 8; j++) acc[i][j] += a * bb[j];
            }
        }
        __syncthreads();
    }
#pragma unroll
    for (int i = 0; i < 4; i++) {
        float s = 0.f, q = 0.f;
#pragma unroll
        for (int j = 0; j < 8; j++) { s += acc[i][j]; q += acc[i][j] * acc[i][j]; }
        ps[tr * 4 + i][tc] = s;
        pq[tr * 4 + i][tc] = q;
    }
    __syncthreads();
    if (tid < 64) {
        float s = 0.f, q = 0.f;
#pragma unroll
        for (int j = 0; j < 16; j++) { s += ps[tid][j]; q += pq[tid][j]; }
        float m = s * (1.f / DM);
        smu[tid] = m;
        srs[tid] = rsqrtf(q * (1.f / DM) - m * m + LNE);
    }
    __syncthreads();
#pragma unroll
    for (int i = 0; i < 4; i++) {
        int r = tr * 4 + i;
        float m = smu[r], rs = srs[r];
#pragma unroll
        for (int j = 0; j < 8; j++)
            g_lnvis[(row0 + r) * DM + tc * 8 + j] = (acc[i][j] - m) * rs;
    }
}

// C = A @ B with K=128.  sel 0..3: A=lnvis -> K0,V0,K1,V1.  sel 4: A=tq -> Qp
__global__ void gemm128_kernel(const float* __restrict__ B, int sel) {
    const float* A;
    float* C;
    if (sel == 4) { A = g_tq; C = g_Qp; }
    else {
        A = g_lnvis;
        C = (sel == 0) ? g_K[0] : (sel == 1) ? g_V[0] : (sel == 2) ? g_K[1] : g_V[1];
    }
    __shared__ float sA[64][33];
    __shared__ float sB[32][132];
    int tid = threadIdx.x;
    int row0 = blockIdx.x * 64;
    int tr = tid >> 4, tc = tid & 15;
    float acc[4][8];
#pragma unroll
    for (int i = 0; i < 4; i++)
#pragma unroll
        for (int j = 0; j < 8; j++) acc[i][j] = 0.f;
    for (int kc = 0; kc < DM; kc += 32) {
#pragma unroll
        for (int i = 0; i < 8; i++) {
            int e = i * 256 + tid, r = e >> 5, k = e & 31;
            sA[r][k] = A[(size_t)(row0 + r) * DM + kc + k];
        }
#pragma unroll
        for (int i = 0; i < 16; i++) {
            int e = i * 256 + tid, k = e >> 7, cc = e & 127;
            sB[k][cc] = B[(kc + k) * DM + cc];
        }
        __syncthreads();
#pragma unroll
        for (int k = 0; k < 32; k++) {
            float4 b0 = *(const float4*)&sB[k][tc * 8];
            float4 b1 = *(const float4*)&sB[k][tc * 8 + 4];
            float bb[8] = {b0.x, b0.y, b0.z, b0.w, b1.x, b1.y, b1.z, b1.w};
#pragma unroll
            for (int i = 0; i < 4; i++) {
                float a = sA[tr * 4 + i][k];
#pragma unroll
                for (int j = 0; j < 8; j++) acc[i][j] += a * bb[j];
            }
        }
        __syncthreads();
    }
#pragma unroll
    for (int i = 0; i < 4; i++) {
        size_t r = row0 + tr * 4 + i;
#pragma unroll
        for (int j = 0; j < 8; j++) C[r * DM + tc * 8 + j] = acc[i][j];
    }
}

// g_tq = LN(g_t) rowwise.  8 rows/block, 256 thr (1 warp per row)
__global__ void ln_rows_kernel() {
    int warp = threadIdx.x >> 5, lane = threadIdx.x & 31;
    size_t row = (size_t)blockIdx.x * 8 + warp;
    const float4* xp = (const float4*)(g_t + row * DM);
    float4 v = xp[lane];
    float s = v.x + v.y + v.z + v.w;
    float q = v.x * v.x + v.y * v.y + v.z * v.z + v.w * v.w;
    s = warp_sum(s);
    q = warp_sum(q);
    float m = s * (1.f / DM);
    float rs = rsqrtf(q * (1.f / DM) - m * m + LNE);
    float4 o = {(v.x - m) * rs, (v.y - m) * rs, (v.z - m) * rs, (v.w - m) * rs};
    ((float4*)(g_tq + row * DM))[lane] = o;
}

// initialize token states to broadcast text
__global__ void init_t_kernel() {
    int idx = blockIdx.x * 256 + threadIdx.x;
    g_t[idx] = g_text[((idx >> 7) & 15) * DM + (idx & 127)];
}

// sliding-window cross attention + residual + LN.  1 block/frame, 128 thr.
__global__ void __launch_bounds__(128) attn_kernel(int l) {
    extern __shared__ float sm[];
    float* sQ = sm;               // 16*128
    float* sR = sQ + NG * DM;     // 16*128
    float* sK = sR + NG * DM;     // 64*128
    float* sV = sK + LQ * DM;     // 64*128
    const float* Kl = g_K[l];
    const float* Vl = g_V[l];
    int tid = threadIdx.x;
    int f = blockIdx.x;
    size_t base = (size_t)f * NG * DM;
#pragma unroll
    for (int i = 0; i < 16; i++) {
        int e = i * 128 + tid;
        sQ[e] = g_Qp[base + e];
        sR[e] = g_tq[base + e];
    }
    for (int w = 0; w < LQ; w++) {
        int src = f - (LQ - 1) + w;
        float kv = 0.f, vv = 0.f;
        if (src >= 0) { kv = Kl[(size_t)src * DM + tid]; vv = Vl[(size_t)src * DM + tid]; }
        sK[w * DM + tid] = kv;
        sV[w * DM + tid] = vv;
    }
    __syncthreads();
    int h = tid >> 4, q = tid & 15;
    float qv[16];
#pragma unroll
    for (int d = 0; d < 16; d++) qv[d] = sQ[q * DM + h * 16 + d];
    float sc[LQ];
    float mx = -1e30f;
#pragma unroll
    for (int k = 0; k < LQ; k++) {
        const float* kr = &sK[k * DM + h * 16];
        float s = 0.f;
#pragma unroll
        for (int d = 0; d < 16; d++) s += qv[d] * kr[d];
        s *= 0.25f;  // 1/sqrt(16)
        sc[k] = s;
        mx = fmaxf(mx, s);
    }
    float sum = 0.f;
#pragma unroll
    for (int k = 0; k < LQ; k++) {
        float e = __expf(sc[k] - mx);
        sc[k] = e;
        sum += e;
    }
    float inv = 1.f / sum;
    float ctx[16];
#pragma unroll
    for (int d = 0; d < 16; d++) ctx[d] = 0.f;
#pragma unroll
    for (int k = 0; k < LQ; k++) {
        float p = sc[k];
        const float* vr = &sV[k * DM + h * 16];
#pragma unroll
        for (int d = 0; d < 16; d++) ctx[d] += p * vr[d];
    }
    __syncthreads();  // all done reading sQ
#pragma unroll
    for (int d = 0; d < 16; d++) sQ[q * DM + h * 16 + d] = ctx[d] * inv;
    __syncthreads();
    // LN(ctx + tq) -> g_t ; 4 warps x 4 rows
    int warp = tid >> 5, lane = tid & 31;
#pragma unroll
    for (int i = 0; i < 4; i++) {
        int r = warp * 4 + i;
        float vals[4];
        float s = 0.f, qq = 0.f;
#pragma unroll
        for (int j = 0; j < 4; j++) {
            int c = lane + 32 * j;
            float v = sQ[r * DM + c] + sR[r * DM + c];
            vals[j] = v;
            s += v;
            qq += v * v;
        }
        s = warp_sum(s);
        qq = warp_sum(qq);
        float m = s * (1.f / DM);
        float rs = rsqrtf(qq * (1.f / DM) - m * m + LNE);
#pragma unroll
        for (int j = 0; j < 4; j++)
            g_t[base + r * DM + lane + 32 * j] = (vals[j] - m) * rs;
    }
}

// fused FFN: t = LN(relu(LN(t)@W1)@W2 + LN(t)).  64 rows/block, 128 thr.
__global__ void __launch_bounds__(128) ffn_kernel(const float* __restrict__ W1l,
                                                  const float* __restrict__ W2l) {
    extern __shared__ float sm[];
    float* sX = sm;                 // 64*128
    float* sW1 = sX + 64 * DM;      // 128*36
    float* sH = sW1 + 128 * 36;     // 64*36
    float* sW2 = sH + 64 * 36;      // 32*132
    __shared__ float ps[64][16], pq[64][16];
    __shared__ float smu[64], srs[64];
    int tid = threadIdx.x;
    size_t row0 = (size_t)blockIdx.x * 64;
    for (int i = 0; i < 64; i++) sX[i * DM + tid] = g_t[(row0 + i) * DM + tid];
    __syncthreads();
    int warp = tid >> 5, lane = tid & 31;
    for (int i = 0; i < 16; i++) {
        int r = warp * 16 + i;
        float s = 0.f, q = 0.f;
#pragma unroll
        for (int j = 0; j < 4; j++) {
            float v = sX[r * DM + lane + 32 * j];
            s += v;
            q += v * v;
        }
        s = warp_sum(s);
        q = warp_sum(q);
        if (lane == 0) {
            float m = s * (1.f / DM);
            smu[r] = m;
            srs[r] = rsqrtf(q * (1.f / DM) - m * m + LNE);
        }
    }
    __syncthreads();
    for (int i = 0; i < 64; i++) {
        float v = sX[i * DM + tid];
        sX[i * DM + tid] = (v - smu[i]) * srs[i];
    }
    __syncthreads();
    int rg = tid >> 4, cg = tid & 15;
    float y[8][8];
#pragma unroll
    for (int i = 0; i < 8; i++)
#pragma unroll
        for (int j = 0; j < 8; j++) y[i][j] = 0.f;
    for (int fc = 0; fc < FD; fc += 32) {
#pragma unroll
        for (int i = 0; i < 32; i++) {
            int e = i * 128 + tid, k = e >> 5, ff = e & 31;
            sW1[k * 36 + ff] = W1l[(size_t)k * FD + fc + ff];
        }
#pragma unroll
        for (int i = 0; i < 32; i++) sW2[i * 132 + tid] = W2l[(size_t)(fc + i) * DM + tid];
        __syncthreads();
        float h0[8], h1[8];
#pragma unroll
        for (int i = 0; i < 8; i++) { h0[i] = 0.f; h1[i] = 0.f; }
        for (int k = 0; k < DM; k++) {
            float b0 = sW1[k * 36 + cg * 2];
            float b1 = sW1[k * 36 + cg * 2 + 1];
#pragma unroll
            for (int i = 0; i < 8; i++) {
                float a = sX[(rg * 8 + i) * DM + k];
                h0[i] += a * b0;
                h1[i] += a * b1;
            }
        }
#pragma unroll
        for (int i = 0; i < 8; i++) {
            sH[(rg * 8 + i) * 36 + cg * 2] = fmaxf(h0[i], 0.f);
            sH[(rg * 8 + i) * 36 + cg * 2 + 1] = fmaxf(h1[i], 0.f);
        }
        __syncthreads();
#pragma unroll
        for (int k = 0; k < 32; k++) {
            float4 c0 = *(const float4*)&sW2[k * 132 + cg * 8];
            float4 c1 = *(const float4*)&sW2[k * 132 + cg * 8 + 4];
            float bb[8] = {c0.x, c0.y, c0.z, c0.w, c1.x, c1.y, c1.z, c1.w};
#pragma unroll
            for (int i = 0; i < 8; i++) {
                float a = sH[(rg * 8 + i) * 36 + k];
#pragma unroll
                for (int j = 0; j < 8; j++) y[i][j] += a * bb[j];
            }
        }
        __syncthreads();
    }
#pragma unroll
    for (int i = 0; i < 8; i++) {
        float s = 0.f, q = 0.f;
#pragma unroll
        for (int j = 0; j < 8; j++) {
            float v = y[i][j] + sX[(rg * 8 + i) * DM + cg * 8 + j];
            s += v;
            q += v * v;
        }
        ps[rg * 8 + i][cg] = s;
        pq[rg * 8 + i][cg] = q;
    }
    __syncthreads();
    if (tid < 64) {
        float s = 0.f, q = 0.f;
#pragma unroll
        for (int j = 0; j < 16; j++) { s += ps[tid][j]; q += pq[tid][j]; }
        float m = s * (1.f / DM);
        smu[tid] = m;
        srs[tid] = rsqrtf(q * (1.f / DM) - m * m + LNE);
    }
    __syncthreads();
#pragma unroll
    for (int i = 0; i < 8; i++) {
        int r = rg * 8 + i;
        float m = smu[r], rs = srs[r];
#pragma unroll
        for (int j = 0; j < 8; j++) {
            float v = y[i][j] + sX[r * DM + cg * 8 + j];
            g_t[(row0 + r) * DM + cg * 8 + j] = (v - m) * rs;
        }
    }
}

// final single-head attention over text.  1 block/frame, 256 thr.
__global__ void final_kernel(const float* __restrict__ Wqf,
                             float* __restrict__ out) {
    __shared__ float st[NG * DM];
    __shared__ float sQ[NG * DM];
    __shared__ float sKf[NG * 132];
    __shared__ float sVf[NG * DM];
    __shared__ float sS[NG][NG + 1];
    int tid = threadIdx.x;
    int f = blockIdx.x;
    size_t base = (size_t)f * NG * DM;
#pragma unroll
    for (int i = 0; i < 8; i++) {
        int e = i * 256 + tid, r = e >> 7, c = e & 127;
        st[e] = g_t[base + e];
        sKf[r * 132 + c] = g_Kf[e];
        sVf[e] = g_Vf[e];
    }
    __syncthreads();
#pragma unroll
    for (int i = 0; i < 8; i++) {
        int e = i * 256 + tid, r = e >> 7, c = e & 127;
        float a = 0.f;
        for (int k = 0; k < DM; k++) a += st[r * DM + k] * Wqf[k * DM + c];
        sQ[e] = a;
    }
    __syncthreads();
    {
        int qr = tid >> 4, kr = tid & 15;
        float a = 0.f;
        for (int k = 0; k < DM; k++) a += sQ[qr * DM + k] * sKf[kr * 132 + k];
        sS[qr][kr] = a * 0.08838834764831843f;  // 1/sqrt(128)
    }
    __syncthreads();
    if (tid < NG) {
        float mx = -1e30f;
#pragma unroll
        for (int k = 0; k < NG; k++) mx = fmaxf(mx, sS[tid][k]);
        float sum = 0.f;
#pragma unroll
        for (int k = 0; k < NG; k++) {
            float e = __expf(sS[tid][k] - mx);
            sS[tid][k] = e;
            sum += e;
        }
        float inv = 1.f / sum;
#pragma unroll
        for (int k = 0; k < NG; k++) sS[tid][k] *= inv;
    }
    __syncthreads();
    // ctx = P @ Vf, add residual t, LN, write out
#pragma unroll
    for (int i = 0; i < 8; i++) {
        int e = i * 256 + tid, r = e >> 7, c = e & 127;
        float a = 0.f;
#pragma unroll
        for (int k = 0; k < NG; k++) a += sS[r][k] * sVf[k * DM + c];
        sQ[e] = a + st[e];  // reuse sQ for pre-LN value
    }
    __syncthreads();
    int warp = tid >> 5, lane = tid & 31;
#pragma unroll
    for (int i = 0; i < 2; i++) {
        int r = warp * 2 + i;
        float4 v0 = *(const float4*)&sQ[r * DM + lane * 4];
        float s = v0.x + v0.y + v0.z + v0.w;
        float q = v0.x * v0.x + v0.y * v0.y + v0.z * v0.z + v0.w * v0.w;
        s = warp_sum(s);
        q = warp_sum(q);
        float m = s * (1.f / DM);
        float rs = rsqrtf(q * (1.f / DM) - m * m + LNE);
        float4 o = {(v0.x - m) * rs, (v0.y - m) * rs, (v0.z - m) * rs, (v0.w - m) * rs};
        *(float4*)&out[base + r * DM + lane * 4] = o;
    }
}

extern "C" void kernel_launch(void* const* d_in, const int* in_sizes, int n_in,
                              void* d_out, int out_size) {
    const float* g    = (const float*)d_in[0];
    const float* LF   = (const float*)d_in[1];
    const float* Wvis = (const float*)d_in[2];
    const float* Wtxt = (const float*)d_in[3];
    const float* Wq   = (const float*)d_in[4];
    const float* Wk   = (const float*)d_in[5];
    const float* Wv   = (const float*)d_in[6];
    const float* W1   = (const float*)d_in[7];
    const float* W2   = (const float*)d_in[8];
    const float* Wqf  = (const float*)d_in[9];
    const float* Wkf  = (const float*)d_in[10];
    const float* Wvf  = (const float*)d_in[11];
    float* out = (float*)d_out;

    const int ATTN_SMEM = (2 * NG * DM + 2 * LQ * DM) * 4;           // 81920
    const int FFN_SMEM  = (64 * DM + 128 * 36 + 64 * 36 + 32 * 132) * 4;  // 77312
    cudaFuncSetAttribute(attn_kernel, cudaFuncAttributeMaxDynamicSharedMemorySize, ATTN_SMEM);
    cudaFuncSetAttribute(ffn_kernel, cudaFuncAttributeMaxDynamicSharedMemorySize, FFN_SMEM);

    visual_ln_kernel<<<TFR / 64, 256>>>(LF, Wvis);
    text_kernel<<<1, 128>>>(g, Wtxt, Wkf, Wvf);
    gemm128_kernel<<<TFR / 64, 256>>>(Wk, 0);                 // K layer0
    gemm128_kernel<<<TFR / 64, 256>>>(Wv, 1);                 // V layer0
    gemm128_kernel<<<TFR / 64, 256>>>(Wk + DM * DM, 2);       // K layer1
    gemm128_kernel<<<TFR / 64, 256>>>(Wv + DM * DM, 3);       // V layer1
    init_t_kernel<<<NTOK * DM / 256, 256>>>();

    for (int l = 0; l < 2; l++) {
        ln_rows_kernel<<<NTOK / 8, 256>>>();                  // tq = LN(t)
        gemm128_kernel<<<NTOK / 64, 256>>>(Wq + l * DM * DM, 4);  // Qp = tq @ Wq
        attn_kernel<<<TFR, 128, ATTN_SMEM>>>(l);
        ffn_kernel<<<NTOK / 64, 128, FFN_SMEM>>>(W1 + (size_t)l * DM * FD,
                                                 W2 + (size_t)l * FD * DM);
    }
    final_kernel<<<TFR, 256>>>(Wqf, out);
}

// round 3
// speedup vs baseline: 1.5420x; 1.5420x over previous
#include <cuda_runtime.h>
#include <cuda_bf16.h>
#include <cstdint>

#define TFR 4096
#define DM 128
#define LQ 64
#define NG 16
#define FD 2048
#define GFD 512
#define NTOK (TFR * NG)
#define LNE 1e-5f

// ---------------- device-global scratch ------------------------------------
__device__ float g_lnvis[TFR * DM];
__device__ float g_text[NG * DM];
__device__ float g_Kf[NG * DM];
__device__ float g_Vf[NG * DM];
__device__ float g_K[2][TFR * DM];
__device__ float g_V[2][TFR * DM];
__device__ float g_t[NTOK * DM];
__device__ float g_tq[NTOK * DM];
__device__ float g_Qp[NTOK * DM];

// split + transposed ([n][k]) weights, bf16 hi/lo
__device__ __nv_bfloat16 g_W1h[2][FD * DM], g_W1l[2][FD * DM];  // [2048][128]
__device__ __nv_bfloat16 g_W2h[2][DM * FD], g_W2l[2][DM * FD];  // [128][2048]
__device__ __nv_bfloat16 g_Wqh[2][DM * DM], g_Wql[2][DM * DM];
__device__ __nv_bfloat16 g_Wkh[2][DM * DM], g_Wkl[2][DM * DM];
__device__ __nv_bfloat16 g_Wvh[2][DM * DM], g_Wvl[2][DM * DM];
__device__ __nv_bfloat16 g_Wqfh[DM * DM], g_Wqfl[DM * DM];

__device__ __forceinline__ float warp_sum(float v) {
#pragma unroll
    for (int o = 16; o > 0; o >>= 1) v += __shfl_xor_sync(0xffffffffu, v, o);
    return v;
}

// ---------------- mma helpers ----------------------------------------------
__device__ __forceinline__ uint32_t cvta_s(const void* p) {
    return (uint32_t)__cvta_generic_to_shared(p);
}
// A fragment m16k16 from row-major [m][k] smem
__device__ __forceinline__ void ldsmA(uint32_t r[4], const __nv_bfloat16* base,
                                      int m0, int k0, int stride, int lane) {
    int grp = lane >> 3, rr = lane & 7;
    int row = m0 + rr + ((grp & 1) << 3);
    int col = k0 + ((grp >> 1) << 3);
    uint32_t a = cvta_s(base + row * stride + col);
    asm volatile("ldmatrix.sync.aligned.m8n8.x4.shared.b16 {%0,%1,%2,%3}, [%4];"
                 : "=r"(r[0]), "=r"(r[1]), "=r"(r[2]), "=r"(r[3]) : "r"(a) : "memory");
}
// B fragments for TWO n8k16 tiles (n0..n0+15) from [n][k] smem
__device__ __forceinline__ void ldsmB(uint32_t r[4], const __nv_bfloat16* base,
                                      int n0, int k0, int stride, int lane) {
    int grp = lane >> 3, rr = lane & 7;
    int row = n0 + rr + ((grp >> 1) << 3);
    int col = k0 + ((grp & 1) << 3);
    uint32_t a = cvta_s(base + row * stride + col);
    asm volatile("ldmatrix.sync.aligned.m8n8.x4.shared.b16 {%0,%1,%2,%3}, [%4];"
                 : "=r"(r[0]), "=r"(r[1]), "=r"(r[2]), "=r"(r[3]) : "r"(a) : "memory");
}
__device__ __forceinline__ void mma16816(float c[4], const uint32_t a[4],
                                         uint32_t b0, uint32_t b1) {
    asm volatile(
        "mma.sync.aligned.m16n8k16.row.col.f32.bf16.bf16.f32 "
        "{%0,%1,%2,%3},{%4,%5,%6,%7},{%8,%9},{%0,%1,%2,%3};"
        : "+f"(c[0]), "+f"(c[1]), "+f"(c[2]), "+f"(c[3])
        : "r"(a[0]), "r"(a[1]), "r"(a[2]), "r"(a[3]), "r"(b0), "r"(b1));
}
__device__ __forceinline__ void split2(float v, __nv_bfloat16& h, __nv_bfloat16& l) {
    h = __float2bfloat16_rn(v);
    l = __float2bfloat16_rn(v - __bfloat162float(h));
}

// ---------------- weight convert: W[K][N] fp32 -> out[n][k] bf16 hi/lo -----
__global__ void split_transpose_kernel(const float* __restrict__ W, int K, int N,
                                       int sel) {
    __nv_bfloat16 *oh, *ol;
    switch (sel) {
        case 0: oh = g_W1h[0]; ol = g_W1l[0]; break;
        case 1: oh = g_W1h[1]; ol = g_W1l[1]; break;
        case 2: oh = g_W2h[0]; ol = g_W2l[0]; break;
        case 3: oh = g_W2h[1]; ol = g_W2l[1]; break;
        case 4: oh = g_Wqh[0]; ol = g_Wql[0]; break;
        case 5: oh = g_Wqh[1]; ol = g_Wql[1]; break;
        case 6: oh = g_Wkh[0]; ol = g_Wkl[0]; break;
        case 7: oh = g_Wkh[1]; ol = g_Wkl[1]; break;
        case 8: oh = g_Wvh[0]; ol = g_Wvl[0]; break;
        case 9: oh = g_Wvh[1]; ol = g_Wvl[1]; break;
        default: oh = g_Wqfh; ol = g_Wqfl; break;
    }
    int idx = blockIdx.x * 256 + threadIdx.x;
    if (idx >= K * N) return;
    int k = idx / N, n = idx - k * N;
    float v = W[idx];
    __nv_bfloat16 h, l;
    split2(v, h, l);
    oh[(size_t)n * K + k] = h;
    ol[(size_t)n * K + k] = l;
}

// ---------------- generic C[M,128] = A[M,128] @ B(hi/lo [128][128]) --------
// asel: 0=lnvis 1=tq 2=t ; bsel: 0..3 Wk0,Wv0,Wk1,Wv1; 4,5 Wq; 6 Wqf
// csel: 0..3 K0,V0,K1,V1; 4 Qp
__global__ void __launch_bounds__(256) mma_gemm128(int asel, int bsel, int csel) {
    const float* A = (asel == 0) ? g_lnvis : (asel == 1) ? g_tq : g_t;
    const __nv_bfloat16 *Bh, *Bl;
    switch (bsel) {
        case 0: Bh = g_Wkh[0]; Bl = g_Wkl[0]; break;
        case 1: Bh = g_Wvh[0]; Bl = g_Wvl[0]; break;
        case 2: Bh = g_Wkh[1]; Bl = g_Wkl[1]; break;
        case 3: Bh = g_Wvh[1]; Bl = g_Wvl[1]; break;
        case 4: Bh = g_Wqh[0]; Bl = g_Wql[0]; break;
        case 5: Bh = g_Wqh[1]; Bl = g_Wql[1]; break;
        default: Bh = g_Wqfh; Bl = g_Wqfl; break;
    }
    float* C = (csel == 0) ? g_K[0] : (csel == 1) ? g_V[0]
             : (csel == 2) ? g_K[1] : (csel == 3) ? g_V[1] : g_Qp;

    extern __shared__ __nv_bfloat16 sm16[];
    __nv_bfloat16* sAh = sm16;                  // [64][136]
    __nv_bfloat16* sAl = sAh + 64 * 136;
    __nv_bfloat16* sBh = sAl + 64 * 136;        // [128][136]
    __nv_bfloat16* sBl = sBh + 128 * 136;
    int tid = threadIdx.x, lane = tid & 31, warp = tid >> 5;
    size_t row0 = (size_t)blockIdx.x * 64;

#pragma unroll
    for (int i = 0; i < 8; i++) {
        int e = i * 256 + tid;               // 2048 float4 groups
        int r = e >> 5, c4 = (e & 31) * 4;
        float4 v = *(const float4*)&A[(row0 + r) * DM + c4];
        __nv_bfloat16 h0, l0, h1, l1, h2, l2, h3, l3;
        split2(v.x, h0, l0); split2(v.y, h1, l1);
        split2(v.z, h2, l2); split2(v.w, h3, l3);
        __nv_bfloat162 ph0; ph0.x = h0; ph0.y = h1;
        __nv_bfloat162 ph1; ph1.x = h2; ph1.y = h3;
        __nv_bfloat162 pl0; pl0.x = l0; pl0.y = l1;
        __nv_bfloat162 pl1; pl1.x = l2; pl1.y = l3;
        *(__nv_bfloat162*)&sAh[r * 136 + c4] = ph0;
        *(__nv_bfloat162*)&sAh[r * 136 + c4 + 2] = ph1;
        *(__nv_bfloat162*)&sAl[r * 136 + c4] = pl0;
        *(__nv_bfloat162*)&sAl[r * 136 + c4 + 2] = pl1;
    }
#pragma unroll
    for (int i = 0; i < 8; i++) {
        int e = i * 256 + tid;               // 2048 uint4 groups
        int n = e >> 4, kk = (e & 15) * 8;
        *(uint4*)&sBh[n * 136 + kk] = *(const uint4*)&Bh[n * DM + kk];
        *(uint4*)&sBl[n * 136 + kk] = *(const uint4*)&Bl[n * DM + kk];
    }
    __syncthreads();

    int wm = warp >> 1, wn = warp & 1;
    int m0 = wm * 16, n0 = wn * 64;
    float acc[8][4];
#pragma unroll
    for (int t = 0; t < 8; t++)
#pragma unroll
        for (int j = 0; j < 4; j++) acc[t][j] = 0.f;

#pragma unroll
    for (int ks = 0; ks < 8; ks++) {
        int k0 = ks * 16;
        uint32_t ah[4], al[4], bh[16], bl[16];
        ldsmA(ah, sAh, m0, k0, 136, lane);
        ldsmA(al, sAl, m0, k0, 136, lane);
#pragma unroll
        for (int j = 0; j < 4; j++) {
            ldsmB(&bh[j * 4], sBh, n0 + 16 * j, k0, 136, lane);
            ldsmB(&bl[j * 4], sBl, n0 + 16 * j, k0, 136, lane);
        }
#pragma unroll
        for (int t = 0; t < 8; t++) {
            int bi = (t >> 1) * 4 + (t & 1) * 2;
            mma16816(acc[t], ah, bh[bi], bh[bi + 1]);
            mma16816(acc[t], al, bh[bi], bh[bi + 1]);
            mma16816(acc[t], ah, bl[bi], bl[bi + 1]);
        }
    }
    int r = m0 + (lane >> 2), cb = (lane & 3) * 2;
#pragma unroll
    for (int t = 0; t < 8; t++) {
        int col = n0 + t * 8 + cb;
        *(float2*)&C[(row0 + r) * DM + col] = make_float2(acc[t][0], acc[t][1]);
        *(float2*)&C[(row0 + r + 8) * DM + col] = make_float2(acc[t][2], acc[t][3]);
    }
}

// ---------------- fused FFN with tensor cores ------------------------------
// t = LN(relu(LN(t)@W1)@W2 + LN(t)), 64 rows/block, 256 thr (8 warps)
__global__ void __launch_bounds__(256) ffn_mma(int l) {
    const __nv_bfloat16* W1h = g_W1h[l];
    const __nv_bfloat16* W1l = g_W1l[l];
    const __nv_bfloat16* W2h = g_W2h[l];
    const __nv_bfloat16* W2l = g_W2l[l];
    extern __shared__ __nv_bfloat16 sm16[];
    __nv_bfloat16* sXh = sm16;                  // [64][136]
    __nv_bfloat16* sXl = sXh + 64 * 136;
    __nv_bfloat16* sW1h = sXl + 64 * 136;       // [64][136] (n-major chunk)
    __nv_bfloat16* sW1l = sW1h + 64 * 136;
    __nv_bfloat16* sHh = sW1l + 64 * 136;       // [64][72]
    __nv_bfloat16* sHl = sHh + 64 * 72;
    __nv_bfloat16* sW2h = sHl + 64 * 72;        // [128][72]
    __nv_bfloat16* sW2l = sW2h + 128 * 72;
    float* sY = (float*)(sW2l + 128 * 72);      // [64][132]

    int tid = threadIdx.x, lane = tid & 31, warp = tid >> 5;
    size_t row0 = (size_t)blockIdx.x * 64;

    // prologue: LN + split X into smem
#pragma unroll
    for (int i = 0; i < 8; i++) {
        int r = warp * 8 + i;
        float4 v = *(const float4*)&g_t[(row0 + r) * DM + lane * 4];
        float s = v.x + v.y + v.z + v.w;
        float q = v.x * v.x + v.y * v.y + v.z * v.z + v.w * v.w;
        s = warp_sum(s); q = warp_sum(q);
        float m = s * (1.f / DM);
        float rs = rsqrtf(q * (1.f / DM) - m * m + LNE);
        float x0 = (v.x - m) * rs, x1 = (v.y - m) * rs;
        float x2 = (v.z - m) * rs, x3 = (v.w - m) * rs;
        __nv_bfloat16 h0, l0, h1, l1, h2, l2, h3, l3;
        split2(x0, h0, l0); split2(x1, h1, l1);
        split2(x2, h2, l2); split2(x3, h3, l3);
        __nv_bfloat162 ph0; ph0.x = h0; ph0.y = h1;
        __nv_bfloat162 ph1; ph1.x = h2; ph1.y = h3;
        __nv_bfloat162 pl0; pl0.x = l0; pl0.y = l1;
        __nv_bfloat162 pl1; pl1.x = l2; pl1.y = l3;
        *(__nv_bfloat162*)&sXh[r * 136 + lane * 4] = ph0;
        *(__nv_bfloat162*)&sXh[r * 136 + lane * 4 + 2] = ph1;
        *(__nv_bfloat162*)&sXl[r * 136 + lane * 4] = pl0;
        *(__nv_bfloat162*)&sXl[r * 136 + lane * 4 + 2] = pl1;
    }
    __syncthreads();

    int wm = warp >> 1, wn = warp & 1;
    int m0 = wm * 16;
    int rr = m0 + (lane >> 2), cb = (lane & 3) * 2;
    float acc2[8][4];
#pragma unroll
    for (int t = 0; t < 8; t++)
#pragma unroll
        for (int j = 0; j < 4; j++) acc2[t][j] = 0.f;

    for (int fc = 0; fc < FD; fc += 64) {
        // load W1 chunk [64 n][128 k] and W2 chunk [128 n][64 k]
#pragma unroll
        for (int i = 0; i < 4; i++) {
            int e = i * 256 + tid;
            int n = e >> 4, kk = (e & 15) * 8;
            *(uint4*)&sW1h[n * 136 + kk] = *(const uint4*)&W1h[(size_t)(fc + n) * DM + kk];
            *(uint4*)&sW1l[n * 136 + kk] = *(const uint4*)&W1l[(size_t)(fc + n) * DM + kk];
        }
#pragma unroll
        for (int i = 0; i < 4; i++) {
            int e = i * 256 + tid;
            int n = e >> 3, kk = (e & 7) * 8;
            *(uint4*)&sW2h[n * 72 + kk] = *(const uint4*)&W2h[(size_t)n * FD + fc + kk];
            *(uint4*)&sW2l[n * 72 + kk] = *(const uint4*)&W2l[(size_t)n * FD + fc + kk];
        }
        __syncthreads();

        // stage1: H = relu(X @ W1c)  [64x64]
        float acc1[4][4];
#pragma unroll
        for (int t = 0; t < 4; t++)
#pragma unroll
            for (int j = 0; j < 4; j++) acc1[t][j] = 0.f;
#pragma unroll
        for (int ks = 0; ks < 8; ks++) {
            int k0 = ks * 16;
            uint32_t ah[4], al[4], bh[8], bl[8];
            ldsmA(ah, sXh, m0, k0, 136, lane);
            ldsmA(al, sXl, m0, k0, 136, lane);
            ldsmB(&bh[0], sW1h, wn * 32, k0, 136, lane);
            ldsmB(&bh[4], sW1h, wn * 32 + 16, k0, 136, lane);
            ldsmB(&bl[0], sW1l, wn * 32, k0, 136, lane);
            ldsmB(&bl[4], sW1l, wn * 32 + 16, k0, 136, lane);
#pragma unroll
            for (int t = 0; t < 4; t++) {
                int bi = (t >> 1) * 4 + (t & 1) * 2;
                mma16816(acc1[t], ah, bh[bi], bh[bi + 1]);
                mma16816(acc1[t], al, bh[bi], bh[bi + 1]);
                mma16816(acc1[t], ah, bl[bi], bl[bi + 1]);
            }
        }
        // relu + split -> sH
#pragma unroll
        for (int t = 0; t < 4; t++) {
            int col = wn * 32 + t * 8 + cb;
            float v0 = fmaxf(acc1[t][0], 0.f), v1 = fmaxf(acc1[t][1], 0.f);
            float v2 = fmaxf(acc1[t][2], 0.f), v3 = fmaxf(acc1[t][3], 0.f);
            __nv_bfloat16 h0, l0, h1, l1, h2, l2, h3, l3;
            split2(v0, h0, l0); split2(v1, h1, l1);
            split2(v2, h2, l2); split2(v3, h3, l3);
            __nv_bfloat162 p;
            p.x = h0; p.y = h1; *(__nv_bfloat162*)&sHh[rr * 72 + col] = p;
            p.x = l0; p.y = l1; *(__nv_bfloat162*)&sHl[rr * 72 + col] = p;
            p.x = h2; p.y = h3; *(__nv_bfloat162*)&sHh[(rr + 8) * 72 + col] = p;
            p.x = l2; p.y = l3; *(__nv_bfloat162*)&sHl[(rr + 8) * 72 + col] = p;
        }
        __syncthreads();

        // stage2: Y += H @ W2c   [64x128]
#pragma unroll
        for (int ks = 0; ks < 4; ks++) {
            int k0 = ks * 16;
            uint32_t ah[4], al[4], bh[16], bl[16];
            ldsmA(ah, sHh, m0, k0, 72, lane);
            ldsmA(al, sHl, m0, k0, 72, lane);
#pragma unroll
            for (int j = 0; j < 4; j++) {
                ldsmB(&bh[j * 4], sW2h, wn * 64 + 16 * j, k0, 72, lane);
                ldsmB(&bl[j * 4], sW2l, wn * 64 + 16 * j, k0, 72, lane);
            }
#pragma unroll
            for (int t = 0; t < 8; t++) {
                int bi = (t >> 1) * 4 + (t & 1) * 2;
                mma16816(acc2[t], ah, bh[bi], bh[bi + 1]);
                mma16816(acc2[t], al, bh[bi], bh[bi + 1]);
                mma16816(acc2[t], ah, bl[bi], bl[bi + 1]);
            }
        }
        __syncthreads();
    }

    // epilogue: Y + residual(x=xh+xl) -> sY, then LN -> g_t
#pragma unroll
    for (int t = 0; t < 8; t++) {
        int col = wn * 64 + t * 8 + cb;
        float r00 = __bfloat162float(sXh[rr * 136 + col]) + __bfloat162float(sXl[rr * 136 + col]);
        float r01 = __bfloat162float(sXh[rr * 136 + col + 1]) + __bfloat162float(sXl[rr * 136 + col + 1]);
        float r10 = __bfloat162float(sXh[(rr + 8) * 136 + col]) + __bfloat162float(sXl[(rr + 8) * 136 + col]);
        float r11 = __bfloat162float(sXh[(rr + 8) * 136 + col + 1]) + __bfloat162float(sXl[(rr + 8) * 136 + col + 1]);
        sY[rr * 132 + col] = acc2[t][0] + r00;
        sY[rr * 132 + col + 1] = acc2[t][1] + r01;
        sY[(rr + 8) * 132 + col] = acc2[t][2] + r10;
        sY[(rr + 8) * 132 + col + 1] = acc2[t][3] + r11;
    }
    __syncthreads();
#pragma unroll
    for (int i = 0; i < 8; i++) {
        int r = warp * 8 + i;
        float4 v = *(const float4*)&sY[r * 132 + lane * 4];
        float s = v.x + v.y + v.z + v.w;
        float q = v.x * v.x + v.y * v.y + v.z * v.z + v.w * v.w;
        s = warp_sum(s); q = warp_sum(q);
        float m = s * (1.f / DM);
        float rs = rsqrtf(q * (1.f / DM) - m * m + LNE);
        float4 o = {(v.x - m) * rs, (v.y - m) * rs, (v.z - m) * rs, (v.w - m) * rs};
        *(float4*)&g_t[(row0 + r) * DM + lane * 4] = o;
    }
}

// ---------------- text = g @ W_txt ; Kf/Vf ---------------------------------
__global__ void text_kernel(const float* __restrict__ g,
                            const float* __restrict__ Wtxt,
                            const float* __restrict__ Wkf,
                            const float* __restrict__ Wvf) {
    __shared__ float sg[NG * GFD];
    int tid = threadIdx.x;
    for (int i = tid; i < NG * GFD; i += 128) sg[i] = g[i];
    __syncthreads();
    int c = tid;
    float acc[NG];
#pragma unroll
    for (int r = 0; r < NG; r++) acc[r] = 0.f;
    for (int k = 0; k < GFD; k++) {
        float w = Wtxt[k * DM + c];
#pragma unroll
        for (int r = 0; r < NG; r++) acc[r] += sg[r * GFD + k] * w;
    }
#pragma unroll
    for (int r = 0; r < NG; r++) g_text[r * DM + c] = acc[r];
    __syncthreads();
    float* st = sg;
#pragma unroll
    for (int r = 0; r < NG; r++) st[r * DM + c] = acc[r];
    __syncthreads();
    float a1[NG], a2[NG];
#pragma unroll
    for (int r = 0; r < NG; r++) { a1[r] = 0.f; a2[r] = 0.f; }
    for (int k = 0; k < DM; k++) {
        float w1 = Wkf[k * DM + c];
        float w2 = Wvf[k * DM + c];
#pragma unroll
        for (int r = 0; r < NG; r++) {
            float tv = st[r * DM + k];
            a1[r] += tv * w1;
            a2[r] += tv * w2;
        }
    }
#pragma unroll
    for (int r = 0; r < NG; r++) {
        g_Kf[r * DM + c] = a1[r];
        g_Vf[r * DM + c] = a2[r];
    }
}

// ---------------- lnvis = LN(long_feature @ W_vis) -------------------------
__global__ void visual_ln_kernel(const float* __restrict__ LF,
                                 const float* __restrict__ Wv) {
    __shared__ float sA[64][33];
    __shared__ float sB[32][132];
    __shared__ float ps[64][16], pq[64][16];
    __shared__ float smu[64], srs[64];
    int tid = threadIdx.x;
    int row0 = blockIdx.x * 64;
    int tr = tid >> 4, tc = tid & 15;
    float acc[4][8];
#pragma unroll
    for (int i = 0; i < 4; i++)
#pragma unroll
        for (int j = 0; j < 8; j++) acc[i][j] = 0.f;
    for (int kc = 0; kc < FD; kc += 32) {
#pragma unroll
        for (int i = 0; i < 8; i++) {
            int e = i * 256 + tid, r = e >> 5, k = e & 31;
            sA[r][k] = LF[(size_t)(row0 + r) * FD + kc + k];
        }
#pragma unroll
        for (int i = 0; i < 16; i++) {
            int e = i * 256 + tid, k = e >> 7, cc = e & 127;
            sB[k][cc] = Wv[(kc + k) * DM + cc];
        }
        __syncthreads();
#pragma unroll
        for (int k = 0; k < 32; k++) {
            float4 b0 = *(const float4*)&sB[k][tc * 8];
            float4 b1 = *(const float4*)&sB[k][tc * 8 + 4];
            float bb[8] = {b0.x, b0.y, b0.z, b0.w, b1.x, b1.y, b1.z, b1.w};
#pragma unroll
            for (int i = 0; i < 4; i++) {
                float a = sA[tr * 4 + i][k];
#pragma unroll
                for (int j = 0; j < 8; j++) acc[i][j] += a * bb[j];
            }
        }
        __syncthreads();
    }
#pragma unroll
    for (int i = 0; i < 4; i++) {
        float s = 0.f, q = 0.f;
#pragma unroll
        for (int j = 0; j < 8; j++) { s += acc[i][j]; q += acc[i][j] * acc[i][j]; }
        ps[tr * 4 + i][tc] = s;
        pq[tr * 4 + i][tc] = q;
    }
    __syncthreads();
    if (tid < 64) {
        float s = 0.f, q = 0.f;
#pragma unroll
        for (int j = 0; j < 16; j++) { s += ps[tid][j]; q += pq[tid][j]; }
        float m = s * (1.f / DM);
        smu[tid] = m;
        srs[tid] = rsqrtf(q * (1.f / DM) - m * m + LNE);
    }
    __syncthreads();
#pragma unroll
    for (int i = 0; i < 4; i++) {
        int r = tr * 4 + i;
        float m = smu[r], rs = srs[r];
#pragma unroll
        for (int j = 0; j < 8; j++)
            g_lnvis[(row0 + r) * DM + tc * 8 + j] = (acc[i][j] - m) * rs;
    }
}

// ---------------- g_tq = LN(g_t) rowwise -----------------------------------
__global__ void ln_rows_kernel() {
    int warp = threadIdx.x >> 5, lane = threadIdx.x & 31;
    size_t row = (size_t)blockIdx.x * 8 + warp;
    const float4* xp = (const float4*)(g_t + row * DM);
    float4 v = xp[lane];
    float s = v.x + v.y + v.z + v.w;
    float q = v.x * v.x + v.y * v.y + v.z * v.z + v.w * v.w;
    s = warp_sum(s); q = warp_sum(q);
    float m = s * (1.f / DM);
    float rs = rsqrtf(q * (1.f / DM) - m * m + LNE);
    float4 o = {(v.x - m) * rs, (v.y - m) * rs, (v.z - m) * rs, (v.w - m) * rs};
    ((float4*)(g_tq + row * DM))[lane] = o;
}

__global__ void init_t_kernel() {
    int idx = blockIdx.x * 256 + threadIdx.x;
    g_t[idx] = g_text[((idx >> 7) & 15) * DM + (idx & 127)];
}

// ---------------- sliding-window cross attention ---------------------------
__global__ void __launch_bounds__(128) attn_kernel(int l) {
    extern __shared__ float sm[];
    float* sQ = sm;
    float* sR = sQ + NG * DM;
    float* sK = sR + NG * DM;
    float* sV = sK + LQ * DM;
    const float* Kl = g_K[l];
    const float* Vl = g_V[l];
    int tid = threadIdx.x;
    int f = blockIdx.x;
    size_t base = (size_t)f * NG * DM;
#pragma unroll
    for (int i = 0; i < 16; i++) {
        int e = i * 128 + tid;
        sQ[e] = g_Qp[base + e];
        sR[e] = g_tq[base + e];
    }
    for (int w = 0; w < LQ; w++) {
        int src = f - (LQ - 1) + w;
        float kv = 0.f, vv = 0.f;
        if (src >= 0) { kv = Kl[(size_t)src * DM + tid]; vv = Vl[(size_t)src * DM + tid]; }
        sK[w * DM + tid] = kv;
        sV[w * DM + tid] = vv;
    }
    __syncthreads();
    int h = tid >> 4, q = tid & 15;
    float qv[16];
#pragma unroll
    for (int d = 0; d < 16; d++) qv[d] = sQ[q * DM + h * 16 + d];
    float sc[LQ];
    float mx = -1e30f;
#pragma unroll
    for (int k = 0; k < LQ; k++) {
        const float* kr = &sK[k * DM + h * 16];
        float s = 0.f;
#pragma unroll
        for (int d = 0; d < 16; d++) s += qv[d] * kr[d];
        s *= 0.25f;
        sc[k] = s;
        mx = fmaxf(mx, s);
    }
    float sum = 0.f;
#pragma unroll
    for (int k = 0; k < LQ; k++) {
        float e = __expf(sc[k] - mx);
        sc[k] = e;
        sum += e;
    }
    float inv = 1.f / sum;
    float ctx[16];
#pragma unroll
    for (int d = 0; d < 16; d++) ctx[d] = 0.f;
#pragma unroll
    for (int k = 0; k < LQ; k++) {
        float p = sc[k];
        const float* vr = &sV[k * DM + h * 16];
#pragma unroll
        for (int d = 0; d < 16; d++) ctx[d] += p * vr[d];
    }
    __syncthreads();
#pragma unroll
    for (int d = 0; d < 16; d++) sQ[q * DM + h * 16 + d] = ctx[d] * inv;
    __syncthreads();
    int warp = tid >> 5, lane = tid & 31;
#pragma unroll
    for (int i = 0; i < 4; i++) {
        int r = warp * 4 + i;
        float vals[4];
        float s = 0.f, qq = 0.f;
#pragma unroll
        for (int j = 0; j < 4; j++) {
            int c = lane + 32 * j;
            float v = sQ[r * DM + c] + sR[r * DM + c];
            vals[j] = v;
            s += v;
            qq += v * v;
        }
        s = warp_sum(s); qq = warp_sum(qq);
        float m = s * (1.f / DM);
        float rs = rsqrtf(qq * (1.f / DM) - m * m + LNE);
#pragma unroll
        for (int j = 0; j < 4; j++)
            g_t[base + r * DM + lane + 32 * j] = (vals[j] - m) * rs;
    }
}

// ---------------- final single-head attention (Q precomputed in g_Qp) ------
__global__ void final_kernel(float* __restrict__ out) {
    __shared__ float st[NG * DM];
    __shared__ float sQ[NG * DM];
    __shared__ float sKf[NG * 132];
    __shared__ float sVf[NG * DM];
    __shared__ float sS[NG][NG + 1];
    int tid = threadIdx.x;
    int f = blockIdx.x;
    size_t base = (size_t)f * NG * DM;
#pragma unroll
    for (int i = 0; i < 8; i++) {
        int e = i * 256 + tid, r = e >> 7, c = e & 127;
        st[e] = g_t[base + e];
        sQ[e] = g_Qp[base + e];
        sKf[r * 132 + c] = g_Kf[e];
        sVf[e] = g_Vf[e];
    }
    __syncthreads();
    {
        int qr = tid >> 4, kr = tid & 15;
        float a = 0.f;
        for (int k = 0; k < DM; k++) a += sQ[qr * DM + k] * sKf[kr * 132 + k];
        sS[qr][kr] = a * 0.08838834764831843f;
    }
    __syncthreads();
    if (tid < NG) {
        float mx = -1e30f;
#pragma unroll
        for (int k = 0; k < NG; k++) mx = fmaxf(mx, sS[tid][k]);
        float sum = 0.f;
#pragma unroll
        for (int k = 0; k < NG; k++) {
            float e = __expf(sS[tid][k] - mx);
            sS[tid][k] = e;
            sum += e;
        }
        float inv = 1.f / sum;
#pragma unroll
        for (int k = 0; k < NG; k++) sS[tid][k] *= inv;
    }
    __syncthreads();
#pragma unroll
    for (int i = 0; i < 8; i++) {
        int e = i * 256 + tid, r = e >> 7, c = e & 127;
        float a = 0.f;
#pragma unroll
        for (int k = 0; k < NG; k++) a += sS[r][k] * sVf[k * DM + c];
        sQ[e] = a + st[e];
    }
    __syncthreads();
    int warp = tid >> 5, lane = tid & 31;
#pragma unroll
    for (int i = 0; i < 2; i++) {
        int r = warp * 2 + i;
        float4 v0 = *(const float4*)&sQ[r * DM + lane * 4];
        float s = v0.x + v0.y + v0.z + v0.w;
        float q = v0.x * v0.x + v0.y * v0.y + v0.z * v0.z + v0.w * v0.w;
        s = warp_sum(s); q = warp_sum(q);
        float m = s * (1.f / DM);
        float rs = rsqrtf(q * (1.f / DM) - m * m + LNE);
        float4 o = {(v0.x - m) * rs, (v0.y - m) * rs, (v0.z - m) * rs, (v0.w - m) * rs};
        *(float4*)&out[base + r * DM + lane * 4] = o;
    }
}

extern "C" void kernel_launch(void* const* d_in, const int* in_sizes, int n_in,
                              void* d_out, int out_size) {
    const float* g    = (const float*)d_in[0];
    const float* LF   = (const float*)d_in[1];
    const float* Wvis = (const float*)d_in[2];
    const float* Wtxt = (const float*)d_in[3];
    const float* Wq   = (const float*)d_in[4];
    const float* Wk   = (const float*)d_in[5];
    const float* Wv   = (const float*)d_in[6];
    const float* W1   = (const float*)d_in[7];
    const float* W2   = (const float*)d_in[8];
    const float* Wqf  = (const float*)d_in[9];
    const float* Wkf  = (const float*)d_in[10];
    const float* Wvf  = (const float*)d_in[11];
    float* out = (float*)d_out;

    const int ATTN_SMEM = (2 * NG * DM + 2 * LQ * DM) * 4;                    // 81920
    const int GEMM_SMEM = (2 * 64 * 136 + 2 * 128 * 136) * 2;                 // 104448
    const int FFN_SMEM  = (4 * 64 * 136 + 2 * 64 * 72 + 2 * 128 * 72) * 2 + 64 * 132 * 4;  // 158720
    cudaFuncSetAttribute(attn_kernel, cudaFuncAttributeMaxDynamicSharedMemorySize, ATTN_SMEM);
    cudaFuncSetAttribute(mma_gemm128, cudaFuncAttributeMaxDynamicSharedMemorySize, GEMM_SMEM);
    cudaFuncSetAttribute(ffn_mma, cudaFuncAttributeMaxDynamicSharedMemorySize, FFN_SMEM);

    // weight conversion (split + transpose)
    split_transpose_kernel<<<(DM * FD + 255) / 256, 256>>>(W1, DM, FD, 0);
    split_transpose_kernel<<<(DM * FD + 255) / 256, 256>>>(W1 + (size_t)DM * FD, DM, FD, 1);
    split_transpose_kernel<<<(FD * DM + 255) / 256, 256>>>(W2, FD, DM, 2);
    split_transpose_kernel<<<(FD * DM + 255) / 256, 256>>>(W2 + (size_t)FD * DM, FD, DM, 3);
    split_transpose_kernel<<<(DM * DM + 255) / 256, 256>>>(Wq, DM, DM, 4);
    split_transpose_kernel<<<(DM * DM + 255) / 256, 256>>>(Wq + DM * DM, DM, DM, 5);
    split_transpose_kernel<<<(DM * DM + 255) / 256, 256>>>(Wk, DM, DM, 6);
    split_transpose_kernel<<<(DM * DM + 255) / 256, 256>>>(Wk + DM * DM, DM, DM, 7);
    split_transpose_kernel<<<(DM * DM + 255) / 256, 256>>>(Wv, DM, DM, 8);
    split_transpose_kernel<<<(DM * DM + 255) / 256, 256>>>(Wv + DM * DM, DM, DM, 9);
    split_transpose_kernel<<<(DM * DM + 255) / 256, 256>>>(Wqf, DM, DM, 10);

    visual_ln_kernel<<<TFR / 64, 256>>>(LF, Wvis);
    text_kernel<<<1, 128>>>(g, Wtxt, Wkf, Wvf);

    mma_gemm128<<<TFR / 64, 256, GEMM_SMEM>>>(0, 0, 0);  // K0
    mma_gemm128<<<TFR / 64, 256, GEMM_SMEM>>>(0, 1, 1);  // V0
    mma_gemm128<<<TFR / 64, 256, GEMM_SMEM>>>(0, 2, 2);  // K1
    mma_gemm128<<<TFR / 64, 256, GEMM_SMEM>>>(0, 3, 3);  // V1
    init_t_kernel<<<NTOK * DM / 256, 256>>>();

    for (int l = 0; l < 2; l++) {
        ln_rows_kernel<<<NTOK / 8, 256>>>();
        mma_gemm128<<<NTOK / 64, 256, GEMM_SMEM>>>(1, 4 + l, 4);  // Qp = tq @ Wq[l]
        attn_kernel<<<TFR, 128, ATTN_SMEM>>>(l);
        ffn_mma<<<NTOK / 64, 256, FFN_SMEM>>>(l);
    }
    mma_gemm128<<<NTOK / 64, 256, GEMM_SMEM>>>(2, 6, 4);  // Qf = t @ Wqf -> g_Qp
    final_kernel<<<TFR, 256>>>(out);
}

// round 4
// speedup vs baseline: 2.8016x; 1.8169x over previous
#include <cuda_runtime.h>
#include <cuda_bf16.h>
#include <cstdint>

#define TFR 4096
#define DM 128
#define LQ 64
#define NG 16
#define FD 2048
#define GFD 512
#define NTOK (TFR * NG)
#define LNE 1e-5f

// ---------------- device-global scratch ------------------------------------
__device__ float g_lnvis[TFR * DM];
__device__ float g_t0ln[NG * DM];
__device__ float g_Q0[NG * DM];
__device__ float g_Kf[NG * DM];
__device__ float g_Vf[NG * DM];
__device__ float g_K[2][TFR * DM];
__device__ float g_V[2][TFR * DM];
__device__ float g_t[NTOK * DM];
__device__ float g_Qp[NTOK * DM];

// split + transposed ([n][k]) weights, bf16 hi/lo
__device__ __nv_bfloat16 g_W1h[2][FD * DM], g_W1l[2][FD * DM];
__device__ __nv_bfloat16 g_W2h[2][DM * FD], g_W2l[2][DM * FD];
__device__ __nv_bfloat16 g_Wqh[2][DM * DM], g_Wql[2][DM * DM];
__device__ __nv_bfloat16 g_Wkh[2][DM * DM], g_Wkl[2][DM * DM];
__device__ __nv_bfloat16 g_Wvh[2][DM * DM], g_Wvl[2][DM * DM];
__device__ __nv_bfloat16 g_Wqfh[DM * DM], g_Wqfl[DM * DM];
__device__ __nv_bfloat16 g_Wvish[DM * FD], g_Wvisl[DM * FD];

__device__ __forceinline__ float warp_sum(float v) {
#pragma unroll
    for (int o = 16; o > 0; o >>= 1) v += __shfl_xor_sync(0xffffffffu, v, o);
    return v;
}
__device__ __forceinline__ uint32_t cvta_s(const void* p) {
    return (uint32_t)__cvta_generic_to_shared(p);
}
__device__ __forceinline__ void ldsmA(uint32_t r[4], const __nv_bfloat16* base,
                                      int m0, int k0, int stride, int lane) {
    int grp = lane >> 3, rr = lane & 7;
    int row = m0 + rr + ((grp & 1) << 3);
    int col = k0 + ((grp >> 1) << 3);
    uint32_t a = cvta_s(base + row * stride + col);
    asm volatile("ldmatrix.sync.aligned.m8n8.x4.shared.b16 {%0,%1,%2,%3}, [%4];"
                 : "=r"(r[0]), "=r"(r[1]), "=r"(r[2]), "=r"(r[3]) : "r"(a) : "memory");
}
__device__ __forceinline__ void ldsmB(uint32_t r[4], const __nv_bfloat16* base,
                                      int n0, int k0, int stride, int lane) {
    int grp = lane >> 3, rr = lane & 7;
    int row = n0 + rr + ((grp >> 1) << 3);
    int col = k0 + ((grp & 1) << 3);
    uint32_t a = cvta_s(base + row * stride + col);
    asm volatile("ldmatrix.sync.aligned.m8n8.x4.shared.b16 {%0,%1,%2,%3}, [%4];"
                 : "=r"(r[0]), "=r"(r[1]), "=r"(r[2]), "=r"(r[3]) : "r"(a) : "memory");
}
__device__ __forceinline__ void mma16816(float c[4], const uint32_t a[4],
                                         uint32_t b0, uint32_t b1) {
    asm volatile(
        "mma.sync.aligned.m16n8k16.row.col.f32.bf16.bf16.f32 "
        "{%0,%1,%2,%3},{%4,%5,%6,%7},{%8,%9},{%0,%1,%2,%3};"
        : "+f"(c[0]), "+f"(c[1]), "+f"(c[2]), "+f"(c[3])
        : "r"(a[0]), "r"(a[1]), "r"(a[2]), "r"(a[3]), "r"(b0), "r"(b1));
}
__device__ __forceinline__ void split2(float v, __nv_bfloat16& h, __nv_bfloat16& l) {
    h = __float2bfloat16_rn(v);
    l = __float2bfloat16_rn(v - __bfloat162float(h));
}
__device__ __forceinline__ uint32_t pack_hi(float a, float b) {
    __nv_bfloat162 p;
    p.x = __float2bfloat16_rn(a);
    p.y = __float2bfloat16_rn(b);
    return *(uint32_t*)&p;
}
__device__ __forceinline__ uint32_t pack_lo(float a, float b) {
    __nv_bfloat16 ha = __float2bfloat16_rn(a), hb = __float2bfloat16_rn(b);
    __nv_bfloat162 p;
    p.x = __float2bfloat16_rn(a - __bfloat162float(ha));
    p.y = __float2bfloat16_rn(b - __bfloat162float(hb));
    return *(uint32_t*)&p;
}

// ---------------- fused weight conversion (one launch) ---------------------
// seg: 0,1 W1 | 2,3 W2 | 4,5 Wq | 6,7 Wk | 8,9 Wv | 10 Wqf | 11 Wvis
__global__ void convert_kernel(const float* W1, const float* W2, const float* Wq,
                               const float* Wk, const float* Wv, const float* Wqf,
                               const float* Wvis) {
    int seg = blockIdx.y;
    const float* src;
    __nv_bfloat16 *oh, *ol;
    int K, N;
    switch (seg) {
        case 0:  src = W1;                 oh = g_W1h[0]; ol = g_W1l[0]; K = DM; N = FD; break;
        case 1:  src = W1 + (size_t)DM*FD; oh = g_W1h[1]; ol = g_W1l[1]; K = DM; N = FD; break;
        case 2:  src = W2;                 oh = g_W2h[0]; ol = g_W2l[0]; K = FD; N = DM; break;
        case 3:  src = W2 + (size_t)FD*DM; oh = g_W2h[1]; ol = g_W2l[1]; K = FD; N = DM; break;
        case 4:  src = Wq;                 oh = g_Wqh[0]; ol = g_Wql[0]; K = DM; N = DM; break;
        case 5:  src = Wq + DM*DM;         oh = g_Wqh[1]; ol = g_Wql[1]; K = DM; N = DM; break;
        case 6:  src = Wk;                 oh = g_Wkh[0]; ol = g_Wkl[0]; K = DM; N = DM; break;
        case 7:  src = Wk + DM*DM;         oh = g_Wkh[1]; ol = g_Wkl[1]; K = DM; N = DM; break;
        case 8:  src = Wv;                 oh = g_Wvh[0]; ol = g_Wvl[0]; K = DM; N = DM; break;
        case 9:  src = Wv + DM*DM;         oh = g_Wvh[1]; ol = g_Wvl[1]; K = DM; N = DM; break;
        case 10: src = Wqf;                oh = g_Wqfh;   ol = g_Wqfl;   K = DM; N = DM; break;
        default: src = Wvis;               oh = g_Wvish;  ol = g_Wvisl;  K = FD; N = DM; break;
    }
    int idx = blockIdx.x * 256 + threadIdx.x;
    if (idx >= K * N) return;
    int k = idx / N, n = idx - k * N;
    float v = src[idx];
    __nv_bfloat16 h, l;
    split2(v, h, l);
    oh[(size_t)n * K + k] = h;
    ol[(size_t)n * K + k] = l;
}

// ---------------- generic 64-row GEMM core, K=128, HMMA 3-pass --------------
__device__ __forceinline__ void gemm128_core(const float* A, float* C,
                                             const __nv_bfloat16* Bh,
                                             const __nv_bfloat16* Bl,
                                             int a_ln, char* smemc) {
    __nv_bfloat16* sAh = (__nv_bfloat16*)smemc;           // [64][136]
    __nv_bfloat16* sAl = sAh + 64 * 136;
    __nv_bfloat16* sBh = sAl + 64 * 136;                  // [128][136]
    __nv_bfloat16* sBl = sBh + 128 * 136;
    int tid = threadIdx.x, lane = tid & 31, warp = tid >> 5;
    size_t row0 = (size_t)blockIdx.x * 64;

#pragma unroll
    for (int i = 0; i < 8; i++) {
        int r = warp * 8 + i;
        float4 v = *(const float4*)&A[(row0 + r) * DM + lane * 4];
        if (a_ln) {
            float s = v.x + v.y + v.z + v.w;
            float q = v.x * v.x + v.y * v.y + v.z * v.z + v.w * v.w;
            s = warp_sum(s); q = warp_sum(q);
            float m = s * (1.f / DM);
            float rs = rsqrtf(q * (1.f / DM) - m * m + LNE);
            v.x = (v.x - m) * rs; v.y = (v.y - m) * rs;
            v.z = (v.z - m) * rs; v.w = (v.w - m) * rs;
        }
        *(uint32_t*)&sAh[r * 136 + lane * 4] = pack_hi(v.x, v.y);
        *(uint32_t*)&sAh[r * 136 + lane * 4 + 2] = pack_hi(v.z, v.w);
        *(uint32_t*)&sAl[r * 136 + lane * 4] = pack_lo(v.x, v.y);
        *(uint32_t*)&sAl[r * 136 + lane * 4 + 2] = pack_lo(v.z, v.w);
    }
#pragma unroll
    for (int i = 0; i < 8; i++) {
        int e = i * 256 + tid;
        int n = e >> 4, kk = (e & 15) * 8;
        *(uint4*)&sBh[n * 136 + kk] = *(const uint4*)&Bh[n * DM + kk];
        *(uint4*)&sBl[n * 136 + kk] = *(const uint4*)&Bl[n * DM + kk];
    }
    __syncthreads();

    int wm = warp >> 1, wn = warp & 1;
    int m0 = wm * 16, n0 = wn * 64;
    float acc[8][4];
#pragma unroll
    for (int t = 0; t < 8; t++)
#pragma unroll
        for (int j = 0; j < 4; j++) acc[t][j] = 0.f;

#pragma unroll
    for (int ks = 0; ks < 8; ks++) {
        int k0 = ks * 16;
        uint32_t ah[4], al[4], bh[16], bl[16];
        ldsmA(ah, sAh, m0, k0, 136, lane);
        ldsmA(al, sAl, m0, k0, 136, lane);
#pragma unroll
        for (int j = 0; j < 4; j++) {
            ldsmB(&bh[j * 4], sBh, n0 + 16 * j, k0, 136, lane);
            ldsmB(&bl[j * 4], sBl, n0 + 16 * j, k0, 136, lane);
        }
#pragma unroll
        for (int t = 0; t < 8; t++) {
            int bi = (t >> 1) * 4 + (t & 1) * 2;
            mma16816(acc[t], ah, bh[bi], bh[bi + 1]);
            mma16816(acc[t], al, bh[bi], bh[bi + 1]);
            mma16816(acc[t], ah, bl[bi], bl[bi + 1]);
        }
    }
    int r = m0 + (lane >> 2), cb = (lane & 3) * 2;
#pragma unroll
    for (int t = 0; t < 8; t++) {
        int col = n0 + t * 8 + cb;
        *(float2*)&C[(row0 + r) * DM + col] = make_float2(acc[t][0], acc[t][1]);
        *(float2*)&C[(row0 + r + 8) * DM + col] = make_float2(acc[t][2], acc[t][3]);
    }
}

// kv: grid (64, 4): y selects K0,V0,K1,V1 (A = lnvis, no LN)
__global__ void __launch_bounds__(256) kv_kernel() {
    extern __shared__ char smc0[];
    int s = blockIdx.y;
    const __nv_bfloat16* Bh = (s == 0) ? g_Wkh[0] : (s == 1) ? g_Wvh[0]
                            : (s == 2) ? g_Wkh[1] : g_Wvh[1];
    const __nv_bfloat16* Bl = (s == 0) ? g_Wkl[0] : (s == 1) ? g_Wvl[0]
                            : (s == 2) ? g_Wkl[1] : g_Wvl[1];
    float* C = (s == 0) ? g_K[0] : (s == 1) ? g_V[0] : (s == 2) ? g_K[1] : g_V[1];
    gemm128_core(g_lnvis, C, Bh, Bl, 0, smc0);
}
// Q projection: mode 0 = Qp layer1 (LN on load), mode 1 = Qf (no LN)
__global__ void __launch_bounds__(256) qproj_kernel(int mode) {
    extern __shared__ char smc1[];
    if (mode == 0)
        gemm128_core(g_t, g_Qp, g_Wqh[1], g_Wql[1], 1, smc1);
    else
        gemm128_core(g_t, g_Qp, g_Wqfh, g_Wqfl, 0, smc1);
}

// ---------------- visual: lnvis = LN(LF @ Wvis), HMMA 3-pass, K=2048 -------
__global__ void __launch_bounds__(256) visual_mma(const float* __restrict__ LF) {
    extern __shared__ char smc2[];
    __nv_bfloat16* sAh = (__nv_bfloat16*)smc2;            // [64][72]
    __nv_bfloat16* sAl = sAh + 64 * 72;
    __nv_bfloat16* sBh = sAl + 64 * 72;                   // [128][72]
    __nv_bfloat16* sBl = sBh + 128 * 72;
    float* sY = (float*)smc2;                             // [64][132] (aliased)
    int tid = threadIdx.x, lane = tid & 31, warp = tid >> 5;
    size_t row0 = (size_t)blockIdx.x * 64;
    int wm = warp >> 1, wn = warp & 1;
    int m0 = wm * 16, n0 = wn * 64;
    float acc[8][4];
#pragma unroll
    for (int t = 0; t < 8; t++)
#pragma unroll
        for (int j = 0; j < 4; j++) acc[t][j] = 0.f;

    for (int kc = 0; kc < FD; kc += 64) {
#pragma unroll
        for (int i = 0; i < 4; i++) {
            int e = i * 256 + tid;
            int r = e >> 4, c4 = (e & 15) * 4;
            float4 v = *(const float4*)&LF[(row0 + r) * FD + kc + c4];
            *(uint32_t*)&sAh[r * 72 + c4] = pack_hi(v.x, v.y);
            *(uint32_t*)&sAh[r * 72 + c4 + 2] = pack_hi(v.z, v.w);
            *(uint32_t*)&sAl[r * 72 + c4] = pack_lo(v.x, v.y);
            *(uint32_t*)&sAl[r * 72 + c4 + 2] = pack_lo(v.z, v.w);
        }
#pragma unroll
        for (int i = 0; i < 4; i++) {
            int e = i * 256 + tid;
            int n = e >> 3, kk = (e & 7) * 8;
            *(uint4*)&sBh[n * 72 + kk] = *(const uint4*)&g_Wvish[(size_t)n * FD + kc + kk];
            *(uint4*)&sBl[n * 72 + kk] = *(const uint4*)&g_Wvisl[(size_t)n * FD + kc + kk];
        }
        __syncthreads();
#pragma unroll
        for (int ks = 0; ks < 4; ks++) {
            int k0 = ks * 16;
            uint32_t ah[4], al[4], bh[16], bl[16];
            ldsmA(ah, sAh, m0, k0, 72, lane);
            ldsmA(al, sAl, m0, k0, 72, lane);
#pragma unroll
            for (int j = 0; j < 4; j++) {
                ldsmB(&bh[j * 4], sBh, n0 + 16 * j, k0, 72, lane);
                ldsmB(&bl[j * 4], sBl, n0 + 16 * j, k0, 72, lane);
            }
#pragma unroll
            for (int t = 0; t < 8; t++) {
                int bi = (t >> 1) * 4 + (t & 1) * 2;
                mma16816(acc[t], ah, bh[bi], bh[bi + 1]);
                mma16816(acc[t], al, bh[bi], bh[bi + 1]);
                mma16816(acc[t], ah, bl[bi], bl[bi + 1]);
            }
        }
        __syncthreads();
    }
    int r = m0 + (lane >> 2), cb = (lane & 3) * 2;
#pragma unroll
    for (int t = 0; t < 8; t++) {
        int col = n0 + t * 8 + cb;
        sY[r * 132 + col] = acc[t][0];
        sY[r * 132 + col + 1] = acc[t][1];
        sY[(r + 8) * 132 + col] = acc[t][2];
        sY[(r + 8) * 132 + col + 1] = acc[t][3];
    }
    __syncthreads();
#pragma unroll
    for (int i = 0; i < 8; i++) {
        int rr = warp * 8 + i;
        float4 v = *(const float4*)&sY[rr * 132 + lane * 4];
        float s = v.x + v.y + v.z + v.w;
        float q = v.x * v.x + v.y * v.y + v.z * v.z + v.w * v.w;
        s = warp_sum(s); q = warp_sum(q);
        float m = s * (1.f / DM);
        float rs = rsqrtf(q * (1.f / DM) - m * m + LNE);
        float4 o = {(v.x - m) * rs, (v.y - m) * rs, (v.z - m) * rs, (v.w - m) * rs};
        *(float4*)&g_lnvis[(row0 + rr) * DM + lane * 4] = o;
    }
}

// ---------------- fused FFN: register-resident H, 128 rows/block ------------
__global__ void __launch_bounds__(256) ffn_mma(int l) {
    const __nv_bfloat16* W1h = g_W1h[l];
    const __nv_bfloat16* W1l = g_W1l[l];
    const __nv_bfloat16* W2h = g_W2h[l];
    const __nv_bfloat16* W2l = g_W2l[l];
    extern __shared__ char smc3[];
    __nv_bfloat16* sXh = (__nv_bfloat16*)smc3;            // [128][136]
    __nv_bfloat16* sXl = sXh + 128 * 136;
    __nv_bfloat16* sW1h = sXl + 128 * 136;                // [64][136]
    __nv_bfloat16* sW1l = sW1h + 64 * 136;
    __nv_bfloat16* sW2h = sW1l + 64 * 136;                // [128][72]
    __nv_bfloat16* sW2l = sW2h + 128 * 72;
    int tid = threadIdx.x, lane = tid & 31, warp = tid >> 5;
    size_t row0 = (size_t)blockIdx.x * 128;
    int m0 = warp * 16;

    // prologue: LN + split X
#pragma unroll
    for (int i = 0; i < 16; i++) {
        int r = warp * 16 + i;
        float4 v = *(const float4*)&g_t[(row0 + r) * DM + lane * 4];
        float s = v.x + v.y + v.z + v.w;
        float q = v.x * v.x + v.y * v.y + v.z * v.z + v.w * v.w;
        s = warp_sum(s); q = warp_sum(q);
        float m = s * (1.f / DM);
        float rs = rsqrtf(q * (1.f / DM) - m * m + LNE);
        v.x = (v.x - m) * rs; v.y = (v.y - m) * rs;
        v.z = (v.z - m) * rs; v.w = (v.w - m) * rs;
        *(uint32_t*)&sXh[r * 136 + lane * 4] = pack_hi(v.x, v.y);
        *(uint32_t*)&sXh[r * 136 + lane * 4 + 2] = pack_hi(v.z, v.w);
        *(uint32_t*)&sXl[r * 136 + lane * 4] = pack_lo(v.x, v.y);
        *(uint32_t*)&sXl[r * 136 + lane * 4 + 2] = pack_lo(v.z, v.w);
    }
    __syncthreads();

    float acc2[16][4];
#pragma unroll
    for (int t = 0; t < 16; t++)
#pragma unroll
        for (int j = 0; j < 4; j++) acc2[t][j] = 0.f;

    for (int fc = 0; fc < FD; fc += 64) {
#pragma unroll
        for (int i = 0; i < 4; i++) {
            int e = i * 256 + tid;
            int n = e >> 4, kk = (e & 15) * 8;
            *(uint4*)&sW1h[n * 136 + kk] = *(const uint4*)&W1h[(size_t)(fc + n) * DM + kk];
            *(uint4*)&sW1l[n * 136 + kk] = *(const uint4*)&W1l[(size_t)(fc + n) * DM + kk];
        }
#pragma unroll
        for (int i = 0; i < 4; i++) {
            int e = i * 256 + tid;
            int n = e >> 3, kk = (e & 7) * 8;
            *(uint4*)&sW2h[n * 72 + kk] = *(const uint4*)&W2h[(size_t)n * FD + fc + kk];
            *(uint4*)&sW2l[n * 72 + kk] = *(const uint4*)&W2l[(size_t)n * FD + fc + kk];
        }
        __syncthreads();

        // stage1: acc1 = X(16 rows) @ W1chunk(64)   3-pass
        float acc1[8][4];
#pragma unroll
        for (int t = 0; t < 8; t++)
#pragma unroll
            for (int j = 0; j < 4; j++) acc1[t][j] = 0.f;
#pragma unroll
        for (int ks = 0; ks < 8; ks++) {
            int k0 = ks * 16;
            uint32_t ah[4], al[4], bh[16], bl[16];
            ldsmA(ah, sXh, m0, k0, 136, lane);
            ldsmA(al, sXl, m0, k0, 136, lane);
#pragma unroll
            for (int j = 0; j < 4; j++) {
                ldsmB(&bh[j * 4], sW1h, 16 * j, k0, 136, lane);
                ldsmB(&bl[j * 4], sW1l, 16 * j, k0, 136, lane);
            }
#pragma unroll
            for (int t = 0; t < 8; t++) {
                int bi = (t >> 1) * 4 + (t & 1) * 2;
                mma16816(acc1[t], ah, bh[bi], bh[bi + 1]);
                mma16816(acc1[t], al, bh[bi], bh[bi + 1]);
                mma16816(acc1[t], ah, bl[bi], bl[bi + 1]);
            }
        }
        // relu + in-register convert: acc layout == A-fragment layout
        uint32_t Hh[4][4], Hl[4][4];
#pragma unroll
        for (int kt = 0; kt < 4; kt++) {
            float p0 = fmaxf(acc1[2 * kt][0], 0.f), p1 = fmaxf(acc1[2 * kt][1], 0.f);
            float p2 = fmaxf(acc1[2 * kt][2], 0.f), p3 = fmaxf(acc1[2 * kt][3], 0.f);
            float q0 = fmaxf(acc1[2 * kt + 1][0], 0.f), q1 = fmaxf(acc1[2 * kt + 1][1], 0.f);
            float q2 = fmaxf(acc1[2 * kt + 1][2], 0.f), q3 = fmaxf(acc1[2 * kt + 1][3], 0.f);
            Hh[kt][0] = pack_hi(p0, p1); Hl[kt][0] = pack_lo(p0, p1);
            Hh[kt][1] = pack_hi(p2, p3); Hl[kt][1] = pack_lo(p2, p3);
            Hh[kt][2] = pack_hi(q0, q1); Hl[kt][2] = pack_lo(q0, q1);
            Hh[kt][3] = pack_hi(q2, q3); Hl[kt][3] = pack_lo(q2, q3);
        }
        // stage2: acc2 += H @ W2chunk
#pragma unroll
        for (int kt = 0; kt < 4; kt++) {
            int k0 = kt * 16;
#pragma unroll
            for (int half = 0; half < 2; half++) {
                uint32_t bh[16], bl[16];
#pragma unroll
                for (int j = 0; j < 4; j++) {
                    ldsmB(&bh[j * 4], sW2h, half * 64 + 16 * j, k0, 72, lane);
                    ldsmB(&bl[j * 4], sW2l, half * 64 + 16 * j, k0, 72, lane);
                }
#pragma unroll
                for (int tt = 0; tt < 8; tt++) {
                    int t = half * 8 + tt;
                    int bi = (tt >> 1) * 4 + (tt & 1) * 2;
                    mma16816(acc2[t], Hh[kt], bh[bi], bh[bi + 1]);
                    mma16816(acc2[t], Hl[kt], bh[bi], bh[bi + 1]);
                    mma16816(acc2[t], Hh[kt], bl[bi], bl[bi + 1]);
                }
            }
        }
        __syncthreads();
    }

    // epilogue: residual + in-warp LN (warp owns rows m0..m0+15 fully)
    int r1 = m0 + (lane >> 2), cb = (lane & 3) * 2;
    float s0 = 0.f, q0 = 0.f, s1 = 0.f, q1 = 0.f;
#pragma unroll
    for (int t = 0; t < 16; t++) {
        int col = t * 8 + cb;
        float x00 = __bfloat162float(sXh[r1 * 136 + col]) + __bfloat162float(sXl[r1 * 136 + col]);
        float x01 = __bfloat162float(sXh[r1 * 136 + col + 1]) + __bfloat162float(sXl[r1 * 136 + col + 1]);
        float x10 = __bfloat162float(sXh[(r1 + 8) * 136 + col]) + __bfloat162float(sXl[(r1 + 8) * 136 + col]);
        float x11 = __bfloat162float(sXh[(r1 + 8) * 136 + col + 1]) + __bfloat162float(sXl[(r1 + 8) * 136 + col + 1]);
        acc2[t][0] += x00; acc2[t][1] += x01;
        acc2[t][2] += x10; acc2[t][3] += x11;
        s0 += acc2[t][0] + acc2[t][1];
        q0 += acc2[t][0] * acc2[t][0] + acc2[t][1] * acc2[t][1];
        s1 += acc2[t][2] + acc2[t][3];
        q1 += acc2[t][2] * acc2[t][2] + acc2[t][3] * acc2[t][3];
    }
#pragma unroll
    for (int o = 1; o <= 2; o <<= 1) {
        s0 += __shfl_xor_sync(0xffffffffu, s0, o);
        q0 += __shfl_xor_sync(0xffffffffu, q0, o);
        s1 += __shfl_xor_sync(0xffffffffu, s1, o);
        q1 += __shfl_xor_sync(0xffffffffu, q1, o);
    }
    float mu0 = s0 * (1.f / DM), rs0 = rsqrtf(q0 * (1.f / DM) - mu0 * mu0 + LNE);
    float mu1 = s1 * (1.f / DM), rs1 = rsqrtf(q1 * (1.f / DM) - mu1 * mu1 + LNE);
#pragma unroll
    for (int t = 0; t < 16; t++) {
        int col = t * 8 + cb;
        *(float2*)&g_t[(row0 + r1) * DM + col] =
            make_float2((acc2[t][0] - mu0) * rs0, (acc2[t][1] - mu0) * rs0);
        *(float2*)&g_t[(row0 + r1 + 8) * DM + col] =
            make_float2((acc2[t][2] - mu1) * rs1, (acc2[t][3] - mu1) * rs1);
    }
}

// ---------------- text: text/Kf/Vf/t0ln/Q0 ---------------------------------
__global__ void text_kernel(const float* __restrict__ g,
                            const float* __restrict__ Wtxt,
                            const float* __restrict__ Wkf,
                            const float* __restrict__ Wvf,
                            const float* __restrict__ Wq0) {
    __shared__ float sg[NG * GFD];
    __shared__ float sln[NG * DM];
    int tid = threadIdx.x;
    for (int i = tid; i < NG * GFD; i += 128) sg[i] = g[i];
    __syncthreads();
    int c = tid;
    float acc[NG];
#pragma unroll
    for (int r = 0; r < NG; r++) acc[r] = 0.f;
    for (int k = 0; k < GFD; k++) {
        float w = Wtxt[k * DM + c];
#pragma unroll
        for (int r = 0; r < NG; r++) acc[r] += sg[r * GFD + k] * w;
    }
    __syncthreads();
    float* st = sg;  // text [16][128]
#pragma unroll
    for (int r = 0; r < NG; r++) st[r * DM + c] = acc[r];
    __syncthreads();
    // Kf/Vf from text
    float a1[NG], a2[NG];
#pragma unroll
    for (int r = 0; r < NG; r++) { a1[r] = 0.f; a2[r] = 0.f; }
    for (int k = 0; k < DM; k++) {
        float w1 = Wkf[k * DM + c];
        float w2 = Wvf[k * DM + c];
#pragma unroll
        for (int r = 0; r < NG; r++) {
            float tv = st[r * DM + k];
            a1[r] += tv * w1;
            a2[r] += tv * w2;
        }
    }
#pragma unroll
    for (int r = 0; r < NG; r++) {
        g_Kf[r * DM + c] = a1[r];
        g_Vf[r * DM + c] = a2[r];
    }
    // t0ln = LN(text), 4 warps x 4 rows
    int warp = tid >> 5, lane = tid & 31;
#pragma unroll
    for (int i = 0; i < 4; i++) {
        int r = warp * 4 + i;
        float4 v = *(const float4*)&st[r * DM + lane * 4];
        float s = v.x + v.y + v.z + v.w;
        float q = v.x * v.x + v.y * v.y + v.z * v.z + v.w * v.w;
        s = warp_sum(s); q = warp_sum(q);
        float m = s * (1.f / DM);
        float rs = rsqrtf(q * (1.f / DM) - m * m + LNE);
        float4 o = {(v.x - m) * rs, (v.y - m) * rs, (v.z - m) * rs, (v.w - m) * rs};
        *(float4*)&sln[r * DM + lane * 4] = o;
        *(float4*)&g_t0ln[r * DM + lane * 4] = o;
    }
    __syncthreads();
    // Q0 = t0ln @ Wq0
    float aq[NG];
#pragma unroll
    for (int r = 0; r < NG; r++) aq[r] = 0.f;
    for (int k = 0; k < DM; k++) {
        float w = Wq0[k * DM + c];
#pragma unroll
        for (int r = 0; r < NG; r++) aq[r] += sln[r * DM + k] * w;
    }
#pragma unroll
    for (int r = 0; r < NG; r++) g_Q0[r * DM + c] = aq[r];
}

// ---------------- sliding-window cross attention ---------------------------
__global__ void __launch_bounds__(128) attn_kernel(int l) {
    extern __shared__ float sm[];
    float* sQ = sm;
    float* sR = sQ + NG * DM;
    float* sK = sR + NG * DM;
    float* sV = sK + LQ * DM;
    const float* Kl = g_K[l];
    const float* Vl = g_V[l];
    int tid = threadIdx.x;
    int f = blockIdx.x;
    size_t base = (size_t)f * NG * DM;
    int warp = tid >> 5, lane = tid & 31;
    if (l == 0) {
#pragma unroll
        for (int i = 0; i < 16; i++) {
            int e = i * 128 + tid;
            sQ[e] = g_Q0[e];
            sR[e] = g_t0ln[e];
        }
    } else {
#pragma unroll
        for (int i = 0; i < 16; i++) {
            int e = i * 128 + tid;
            sQ[e] = g_Qp[base + e];
        }
#pragma unroll
        for (int i = 0; i < 4; i++) {
            int r = warp * 4 + i;
            float4 v = *(const float4*)&g_t[base + r * DM + lane * 4];
            float s = v.x + v.y + v.z + v.w;
            float q = v.x * v.x + v.y * v.y + v.z * v.z + v.w * v.w;
            s = warp_sum(s); q = warp_sum(q);
            float m = s * (1.f / DM);
            float rs = rsqrtf(q * (1.f / DM) - m * m + LNE);
            float4 o = {(v.x - m) * rs, (v.y - m) * rs, (v.z - m) * rs, (v.w - m) * rs};
            *(float4*)&sR[r * DM + lane * 4] = o;
        }
    }
    for (int w = 0; w < LQ; w++) {
        int src = f - (LQ - 1) + w;
        float kv = 0.f, vv = 0.f;
        if (src >= 0) { kv = Kl[(size_t)src * DM + tid]; vv = Vl[(size_t)src * DM + tid]; }
        sK[w * DM + tid] = kv;
        sV[w * DM + tid] = vv;
    }
    __syncthreads();
    int h = tid >> 4, q = tid & 15;
    float qv[16];
#pragma unroll
    for (int d = 0; d < 16; d++) qv[d] = sQ[q * DM + h * 16 + d];
    float sc[LQ];
    float mx = -1e30f;
#pragma unroll
    for (int k = 0; k < LQ; k++) {
        const float* kr = &sK[k * DM + h * 16];
        float s = 0.f;
#pragma unroll
        for (int d = 0; d < 16; d++) s += qv[d] * kr[d];
        s *= 0.25f;
        sc[k] = s;
        mx = fmaxf(mx, s);
    }
    float sum = 0.f;
#pragma unroll
    for (int k = 0; k < LQ; k++) {
        float e = __expf(sc[k] - mx);
        sc[k] = e;
        sum += e;
    }
    float inv = 1.f / sum;
    float ctx[16];
#pragma unroll
    for (int d = 0; d < 16; d++) ctx[d] = 0.f;
#pragma unroll
    for (int k = 0; k < LQ; k++) {
        float p = sc[k];
        const float* vr = &sV[k * DM + h * 16];
#pragma unroll
        for (int d = 0; d < 16; d++) ctx[d] += p * vr[d];
    }
    __syncthreads();
#pragma unroll
    for (int d = 0; d < 16; d++) sQ[q * DM + h * 16 + d] = ctx[d] * inv;
    __syncthreads();
#pragma unroll
    for (int i = 0; i < 4; i++) {
        int r = warp * 4 + i;
        float vals[4];
        float s = 0.f, qq = 0.f;
#pragma unroll
        for (int j = 0; j < 4; j++) {
            int cc = lane + 32 * j;
            float v = sQ[r * DM + cc] + sR[r * DM + cc];
            vals[j] = v;
            s += v;
            qq += v * v;
        }
        s = warp_sum(s); qq = warp_sum(qq);
        float m = s * (1.f / DM);
        float rs = rsqrtf(qq * (1.f / DM) - m * m + LNE);
#pragma unroll
        for (int j = 0; j < 4; j++)
            g_t[base + r * DM + lane + 32 * j] = (vals[j] - m) * rs;
    }
}

// ---------------- final single-head attention ------------------------------
__global__ void final_kernel(float* __restrict__ out) {
    __shared__ float st[NG * DM];
    __shared__ float sQ[NG * DM];
    __shared__ float sKf[NG * 132];
    __shared__ float sVf[NG * DM];
    __shared__ float sS[NG][NG + 1];
    int tid = threadIdx.x;
    int f = blockIdx.x;
    size_t base = (size_t)f * NG * DM;
#pragma unroll
    for (int i = 0; i < 8; i++) {
        int e = i * 256 + tid, r = e >> 7, c = e & 127;
        st[e] = g_t[base + e];
        sQ[e] = g_Qp[base + e];
        sKf[r * 132 + c] = g_Kf[e];
        sVf[e] = g_Vf[e];
    }
    __syncthreads();
    {
        int qr = tid >> 4, kr = tid & 15;
        float a = 0.f;
        for (int k = 0; k < DM; k++) a += sQ[qr * DM + k] * sKf[kr * 132 + k];
        sS[qr][kr] = a * 0.08838834764831843f;
    }
    __syncthreads();
    if (tid < NG) {
        float mx = -1e30f;
#pragma unroll
        for (int k = 0; k < NG; k++) mx = fmaxf(mx, sS[tid][k]);
        float sum = 0.f;
#pragma unroll
        for (int k = 0; k < NG; k++) {
            float e = __expf(sS[tid][k] - mx);
            sS[tid][k] = e;
            sum += e;
        }
        float inv = 1.f / sum;
#pragma unroll
        for (int k = 0; k < NG; k++) sS[tid][k] *= inv;
    }
    __syncthreads();
#pragma unroll
    for (int i = 0; i < 8; i++) {
        int e = i * 256 + tid, r = e >> 7, c = e & 127;
        float a = 0.f;
#pragma unroll
        for (int k = 0; k < NG; k++) a += sS[r][k] * sVf[k * DM + c];
        sQ[e] = a + st[e];
    }
    __syncthreads();
    int warp = tid >> 5, lane = tid & 31;
#pragma unroll
    for (int i = 0; i < 2; i++) {
        int r = warp * 2 + i;
        float4 v0 = *(const float4*)&sQ[r * DM + lane * 4];
        float s = v0.x + v0.y + v0.z + v0.w;
        float q = v0.x * v0.x + v0.y * v0.y + v0.z * v0.z + v0.w * v0.w;
        s = warp_sum(s); q = warp_sum(q);
        float m = s * (1.f / DM);
        float rs = rsqrtf(q * (1.f / DM) - m * m + LNE);
        float4 o = {(v0.x - m) * rs, (v0.y - m) * rs, (v0.z - m) * rs, (v0.w - m) * rs};
        *(float4*)&out[base + r * DM + lane * 4] = o;
    }
}

extern "C" void kernel_launch(void* const* d_in, const int* in_sizes, int n_in,
                              void* d_out, int out_size) {
    const float* g    = (const float*)d_in[0];
    const float* LF   = (const float*)d_in[1];
    const float* Wvis = (const float*)d_in[2];
    const float* Wtxt = (const float*)d_in[3];
    const float* Wq   = (const float*)d_in[4];
    const float* Wk   = (const float*)d_in[5];
    const float* Wv   = (const float*)d_in[6];
    const float* W1   = (const float*)d_in[7];
    const float* W2   = (const float*)d_in[8];
    const float* Wqf  = (const float*)d_in[9];
    const float* Wkf  = (const float*)d_in[10];
    const float* Wvf  = (const float*)d_in[11];
    float* out = (float*)d_out;

    const int ATTN_SMEM = (2 * NG * DM + 2 * LQ * DM) * 4;            // 81920
    const int GEMM_SMEM = (2 * 64 * 136 + 2 * 128 * 136) * 2;         // 104448
    const int VIS_SMEM  = (2 * 64 * 72 + 2 * 128 * 72) * 2;           // 55296
    const int FFN_SMEM  = (2 * 128 * 136 + 2 * 64 * 136 + 2 * 128 * 72) * 2;  // 141312
    cudaFuncSetAttribute(attn_kernel, cudaFuncAttributeMaxDynamicSharedMemorySize, ATTN_SMEM);
    cudaFuncSetAttribute(kv_kernel, cudaFuncAttributeMaxDynamicSharedMemorySize, GEMM_SMEM);
    cudaFuncSetAttribute(qproj_kernel, cudaFuncAttributeMaxDynamicSharedMemorySize, GEMM_SMEM);
    cudaFuncSetAttribute(visual_mma, cudaFuncAttributeMaxDynamicSharedMemorySize, VIS_SMEM);
    cudaFuncSetAttribute(ffn_mma, cudaFuncAttributeMaxDynamicSharedMemorySize, FFN_SMEM);

    convert_kernel<<<dim3(1024, 12), 256>>>(W1, W2, Wq, Wk, Wv, Wqf, Wvis);   // 0
    text_kernel<<<1, 128>>>(g, Wtxt, Wkf, Wvf, Wq);                           // 1
    visual_mma<<<TFR / 64, 256, VIS_SMEM>>>(LF);                              // 2
    kv_kernel<<<dim3(TFR / 64, 4), 256, GEMM_SMEM>>>();                       // 3
    attn_kernel<<<TFR, 128, ATTN_SMEM>>>(0);                                  // 4
    ffn_mma<<<NTOK / 128, 256, FFN_SMEM>>>(0);                                // 5 <- profiled
    qproj_kernel<<<NTOK / 64, 256, GEMM_SMEM>>>(0);                           // 6
    attn_kernel<<<TFR, 128, ATTN_SMEM>>>(1);                                  // 7
    ffn_mma<<<NTOK / 128, 256, FFN_SMEM>>>(1);                                // 8
    qproj_kernel<<<NTOK / 64, 256, GEMM_SMEM>>>(1);                           // 9
    final_kernel<<<TFR, 256>>>(out);                                          // 10
}